// round 4
// baseline (speedup 1.0000x reference)
#include <cuda_runtime.h>
#include <cstdint>

// NCA: x[8,20,256,256], W1[128,60], b1[128], W2[20,128], steps=64

#define BB 8
#define CC 20
#define HH 256
#define WW 256
#define KH 128
#define TILE_W 32
#define TILE_H 16
#define NPIX (TILE_W*TILE_H)      // 512
#define NTHREADS 512
#define NCHUNK 8
#define KCHUNK 16                 // 128 / 8

#define XS_ROWS (TILE_H+2)        // 18
#define XS_ELEMS (CC*XS_ROWS*34)  // 12240
#define PS_ELEMS (NPIX*60)        // 30720
#define W1_ELEMS (KH*60)          // 7680
#define W2_ELEMS (KH*20)          // 2560
#define SMEM_FLOATS (XS_ELEMS + PS_ELEMS + W1_ELEMS + W2_ELEMS + KH)
#define SMEM_BYTES  (SMEM_FLOATS*4 + (2*NPIX+1)*4)   // ~217.4 KB

__device__ float g_bufA[BB*CC*HH*WW];
__device__ float g_bufB[BB*CC*HH*WW];

__device__ __forceinline__ uint32_t rotl32(uint32_t v, int r) {
    return (v << r) | (v >> (32 - r));
}

// JAX threefry2x32 (20 rounds), bit-exact (verified vs Random123 KAT).
__device__ __forceinline__ void tf2x32(uint32_t k0, uint32_t k1,
                                       uint32_t& x0, uint32_t& x1) {
    uint32_t ks2 = k0 ^ k1 ^ 0x1BD11BDAu;
    x0 += k0; x1 += k1;
#define TFR(r) { x0 += x1; x1 = rotl32(x1, r); x1 ^= x0; }
    TFR(13) TFR(15) TFR(26) TFR(6)
    x0 += k1; x1 += ks2 + 1u;
    TFR(17) TFR(29) TFR(16) TFR(24)
    x0 += ks2; x1 += k0 + 2u;
    TFR(13) TFR(15) TFR(26) TFR(6)
    x0 += k0; x1 += k1 + 3u;
    TFR(17) TFR(29) TFR(16) TFR(24)
    x0 += k1; x1 += ks2 + 4u;
    TFR(13) TFR(15) TFR(26) TFR(6)
    x0 += ks2; x1 += k0 + 5u;
#undef TFR
}

__device__ __forceinline__ int refl(int v, int n) {
    v = (v < 0) ? -v : v;
    return (v >= n) ? (2 * n - 2 - v) : v;
}

__global__ void __launch_bounds__(NTHREADS, 1)
nca_step(const float* __restrict__ in, float* __restrict__ out,
         const float* __restrict__ W1, const float* __restrict__ b1,
         const float* __restrict__ W2, int step)
{
    extern __shared__ float sm[];
    float* xs  = sm;                      // [20][18][34]  (dead after p-phase)
    float* dxs = sm;                      // [F][20] overlays xs after p-phase
    float* ps  = xs + XS_ELEMS;           // [512][60]
    float* W1s = ps + PS_ELEMS;           // [128][60]
    float* W2s = W1s + W1_ELEMS;          // [128][20] (k-major)
    float* b1s = W2s + W2_ELEMS;          // [128]
    int*   lst    = (int*)(b1s + KH);     // [512] compaction pos -> tid
    int*   pos_of = lst + NPIX;           // [512] tid -> compaction pos (or -1)
    int*   cntp   = pos_of + NPIX;

    const int tid = threadIdx.x;
    const int bz  = blockIdx.z;
    const int by0 = blockIdx.y * TILE_H;
    const int bx0 = blockIdx.x * TILE_W;

    if (tid == 0) *cntp = 0;

    // ---- stage xs tile (reflect halo) + weights ----
    const float* inb = in + bz * (CC * HH * WW);
    for (int i = tid; i < XS_ELEMS; i += NTHREADS) {
        int c   = i / (XS_ROWS * 34);
        int rem = i - c * (XS_ROWS * 34);
        int yy  = rem / 34;
        int xx  = rem - yy * 34;
        int gy  = refl(by0 + yy - 1, HH);
        int gx  = refl(bx0 + xx - 1, WW);
        xs[i] = inb[(c << 16) + (gy << 8) + gx];
    }
    for (int i = tid; i < W1_ELEMS; i += NTHREADS) W1s[i] = W1[i];
    for (int i = tid; i < W2_ELEMS; i += NTHREADS) {
        int k = i / 20; int c = i - k * 20;
        W2s[i] = W2[c * KH + k];
    }
    if (tid < KH) b1s[tid] = b1[tid];

    __syncthreads();

    const int tx = tid & 31, ty = tid >> 5;        // 32 x 16
    const int gy = by0 + ty, gx = bx0 + tx;
    const int pidx = (bz << 16) + (gy << 8) + gx;

    // ---- fire mask (partitionable threefry, XOR-fold) ----
    uint32_t s0 = 0u, s1 = (uint32_t)step;
    tf2x32(0u, 42u, s0, s1);                   // fold_in(key(42), step)
    uint32_t x0 = 0u, x1 = (uint32_t)pidx;     // block = (0, flat_idx)
    tf2x32(s0, s1, x0, x1);
    uint32_t bits = x0 ^ x1;
    bool fire = (bits & 0x80000000u) == 0u;

    float* outb = out + bz * (CC * HH * WW);

    if (!fire) {
        pos_of[tid] = -1;
        #pragma unroll
        for (int c = 0; c < CC; c++)
            outb[(c << 16) + (gy << 8) + gx] = xs[(c * XS_ROWS + ty + 1) * 34 + tx + 1];
    } else {
        int pos = atomicAdd(cntp, 1);
        lst[pos] = tid;
        pos_of[tid] = pos;
    }
    __syncthreads();

    const int F = *cntp;

    // ---- perceive phase: ps[i][60] for all firing pixels (cooperative) ----
    for (int j = tid; j < F * CC; j += NTHREADS) {
        int i = j / CC;
        int c = j - i * CC;
        int pt = lst[i];
        int px = pt & 31, py = pt >> 5;
        const float* b = xs + (c * XS_ROWS + py) * 34 + px;
        float a00 = b[0],  a01 = b[1],  a02 = b[2];
        float a10 = b[34], a11 = b[35], a12 = b[36];
        float a20 = b[68], a21 = b[69], a22 = b[70];
        float* pr = ps + i * 60;
        pr[c]          = a11;
        pr[20 + 2 * c] = (a02 - a00 + 2.f * (a12 - a10) + a22 - a20) * 0.125f;
        pr[21 + 2 * c] = (a20 - a00 + 2.f * (a21 - a01) + a22 - a02) * 0.125f;
    }
    __syncthreads();
    // xs is now dead; dxs overlays it.
    for (int j = tid; j < F * CC; j += NTHREADS) dxs[j] = 0.f;
    __syncthreads();

    // ---- matvec work queue: F*8 units (chunk-major -> warp-broadcast W loads) ----
    const int NU = F * NCHUNK;
    for (int u = tid; u < NU; u += NTHREADS) {
        int chunk = u / F;
        int i     = u - chunk * F;
        int k0    = chunk * KCHUNK;

        float p[60];
        const float4* pr4 = (const float4*)(ps + i * 60);
        #pragma unroll
        for (int q = 0; q < 15; q++) {
            float4 t = pr4[q];
            p[4*q+0] = t.x; p[4*q+1] = t.y; p[4*q+2] = t.z; p[4*q+3] = t.w;
        }

        float dx[20];
        #pragma unroll
        for (int c = 0; c < 20; c++) dx[c] = 0.f;

        #pragma unroll 4
        for (int k = k0; k < k0 + KCHUNK; k++) {
            const float4* wr = (const float4*)(W1s + k * 60);
            float acc0 = 0.f, acc1 = 0.f, acc2 = 0.f, acc3 = 0.f;
            #pragma unroll
            for (int q = 0; q < 15; q++) {
                float4 w = wr[q];
                acc0 += w.x * p[4*q+0];
                acc1 += w.y * p[4*q+1];
                acc2 += w.z * p[4*q+2];
                acc3 += w.w * p[4*q+3];
            }
            float hk = (acc0 + acc1) + (acc2 + acc3) + b1s[k];
            hk = fmaxf(hk, 0.f);
            const float4* w2r = (const float4*)(W2s + k * 20);
            #pragma unroll
            for (int q = 0; q < 5; q++) {
                float4 w = w2r[q];
                dx[4*q+0] += w.x * hk;
                dx[4*q+1] += w.y * hk;
                dx[4*q+2] += w.z * hk;
                dx[4*q+3] += w.w * hk;
            }
        }

        float* dr = dxs + i * 20;
        #pragma unroll
        for (int c = 0; c < 20; c++) atomicAdd(dr + c, dx[c]);
    }
    __syncthreads();

    // ---- writeout for firing pixels (owner thread, coalesced) ----
    const int mypos = pos_of[tid];
    if (mypos >= 0) {
        const float* pr = ps  + mypos * 60;   // pr[c] = center value
        const float* dr = dxs + mypos * 20;
        #pragma unroll
        for (int c = 0; c < CC; c++) {
            float v = pr[c];
            if (c >= 3) v += dr[c];           // image channels immutable
            outb[(c << 16) + (gy << 8) + gx] = v;
        }
    }
}

extern "C" void kernel_launch(void* const* d_in, const int* in_sizes, int n_in,
                              void* d_out, int out_size) {
    // Identify inputs by unique element counts:
    // x=10485760, W1=7680, b1=128, W2=2560, steps=1
    const float* x = nullptr; const float* W1 = nullptr;
    const float* b1 = nullptr; const float* W2 = nullptr;
    for (int i = 0; i < n_in; i++) {
        switch (in_sizes[i]) {
            case BB*CC*HH*WW: x  = (const float*)d_in[i]; break;
            case W1_ELEMS:    W1 = (const float*)d_in[i]; break;
            case KH:          b1 = (const float*)d_in[i]; break;
            case W2_ELEMS:    W2 = (const float*)d_in[i]; break;
            default: break; // steps scalar; fixed at 64
        }
    }
    float* out = (float*)d_out;

    float *bufA = nullptr, *bufB = nullptr;
    cudaGetSymbolAddress((void**)&bufA, g_bufA);
    cudaGetSymbolAddress((void**)&bufB, g_bufB);

    cudaFuncSetAttribute(nca_step, cudaFuncAttributeMaxDynamicSharedMemorySize,
                         SMEM_BYTES);

    dim3 grid(WW / TILE_W, HH / TILE_H, BB);   // (8, 16, 8) = 1024 blocks
    const int STEPS = 64;
    for (int s = 0; s < STEPS; s++) {
        const float* src = (s == 0) ? x : ((s & 1) ? bufA : bufB);
        float* dst = (s == STEPS - 1) ? out : ((s & 1) ? bufB : bufA);
        nca_step<<<grid, NTHREADS, SMEM_BYTES>>>(src, dst, W1, b1, W2, s);
    }
}

// round 5
// speedup vs baseline: 1.1279x; 1.1279x over previous
#include <cuda_runtime.h>
#include <cstdint>

// NCA: x[8,20,256,256], W1[128,60], b1[128], W2[20,128], steps=64

#define BB 8
#define CC 20
#define HH 256
#define WW 256
#define KH 128
#define TILE_W 32
#define TILE_H 16
#define NPIX (TILE_W*TILE_H)      // 512
#define NTHREADS 512
#define KHALF 64

#define XS_ROWS (TILE_H+2)        // 18
#define XS_ELEMS (CC*XS_ROWS*34)  // 12240
#define W1_ELEMS (KH*60)          // 7680
#define W2_ELEMS (KH*20)          // 2560
#define DXS_ROWS 384              // F ~ Bin(512,.5): mean 256, sd 11.3 -> 384 is +11 sd
#define DXS_STRIDE 42             // floats; even (8B-aligned rows), odd/2 banks ok
#define SMEM_FLOATS (XS_ELEMS + W1_ELEMS + W2_ELEMS + KH + DXS_ROWS*DXS_STRIDE)
#define SMEM_BYTES  (SMEM_FLOATS*4 + (2*NPIX+1)*4)

__device__ float g_bufA[BB*CC*HH*WW];
__device__ float g_bufB[BB*CC*HH*WW];

typedef unsigned long long u64;

__device__ __forceinline__ u64 fma2(u64 a, u64 b, u64 c) {
    u64 d;
    asm("fma.rn.f32x2 %0, %1, %2, %3;" : "=l"(d) : "l"(a), "l"(b), "l"(c));
    return d;
}
__device__ __forceinline__ u64 pack2(float lo, float hi) {
    u64 r;
    asm("mov.b64 %0, {%1, %2};" : "=l"(r) : "f"(lo), "f"(hi));
    return r;
}
__device__ __forceinline__ void unpack2(float& lo, float& hi, u64 v) {
    asm("mov.b64 {%0, %1}, %2;" : "=f"(lo), "=f"(hi) : "l"(v));
}

__device__ __forceinline__ uint32_t rotl32(uint32_t v, int r) {
    return (v << r) | (v >> (32 - r));
}

// JAX threefry2x32 (20 rounds), bit-exact.
__device__ __forceinline__ void tf2x32(uint32_t k0, uint32_t k1,
                                       uint32_t& x0, uint32_t& x1) {
    uint32_t ks2 = k0 ^ k1 ^ 0x1BD11BDAu;
    x0 += k0; x1 += k1;
#define TFR(r) { x0 += x1; x1 = rotl32(x1, r); x1 ^= x0; }
    TFR(13) TFR(15) TFR(26) TFR(6)
    x0 += k1; x1 += ks2 + 1u;
    TFR(17) TFR(29) TFR(16) TFR(24)
    x0 += ks2; x1 += k0 + 2u;
    TFR(13) TFR(15) TFR(26) TFR(6)
    x0 += k0; x1 += k1 + 3u;
    TFR(17) TFR(29) TFR(16) TFR(24)
    x0 += k1; x1 += ks2 + 4u;
    TFR(13) TFR(15) TFR(26) TFR(6)
    x0 += ks2; x1 += k0 + 5u;
#undef TFR
}

__device__ __forceinline__ int refl(int v, int n) {
    v = (v < 0) ? -v : v;
    return (v >= n) ? (2 * n - 2 - v) : v;
}

struct ull2 { u64 x, y; };

__global__ void __launch_bounds__(NTHREADS, 1)
nca_step(const float* __restrict__ in, float* __restrict__ out,
         const float* __restrict__ W1, const float* __restrict__ b1,
         const float* __restrict__ W2, int step)
{
    extern __shared__ float sm[];
    float* xs  = sm;                      // [20][18][34]
    float* W1s = xs + XS_ELEMS;           // [128][60]   (240B rows, 16B aligned)
    float* W2s = W1s + W1_ELEMS;          // [128][20]   (k-major, 80B rows)
    float* b1s = W2s + W2_ELEMS;          // [128]
    float* dxs = b1s + KH;                // [384][42]: [pos][half*20 + c]
    int*   lst    = (int*)(dxs + DXS_ROWS*DXS_STRIDE); // [512]
    int*   pos_of = lst + NPIX;                        // [512]
    int*   cntp   = pos_of + NPIX;

    const int tid = threadIdx.x;
    const int bz  = blockIdx.z;
    const int by0 = blockIdx.y * TILE_H;
    const int bx0 = blockIdx.x * TILE_W;

    if (tid == 0) *cntp = 0;

    // ---- stage tile + weights ----
    const float* inb = in + bz * (CC * HH * WW);
    for (int i = tid; i < XS_ELEMS; i += NTHREADS) {
        int c   = i / (XS_ROWS * 34);
        int rem = i - c * (XS_ROWS * 34);
        int yy  = rem / 34;
        int xx  = rem - yy * 34;
        int gy  = refl(by0 + yy - 1, HH);
        int gx  = refl(bx0 + xx - 1, WW);
        xs[i] = inb[(c << 16) + (gy << 8) + gx];
    }
    for (int i = tid; i < W1_ELEMS; i += NTHREADS) W1s[i] = W1[i];
    for (int i = tid; i < W2_ELEMS; i += NTHREADS) {
        int k = i / 20; int c = i - k * 20;
        W2s[i] = W2[c * KH + k];
    }
    if (tid < KH) b1s[tid] = b1[tid];

    __syncthreads();

    const int tx = tid & 31, ty = tid >> 5;        // 32 x 16 tile
    const int gy = by0 + ty, gx = bx0 + tx;
    const int pidx = (bz << 16) + (gy << 8) + gx;

    // ---- fire mask (partitionable threefry, XOR-fold) ----
    uint32_t s0 = 0u, s1 = (uint32_t)step;
    tf2x32(0u, 42u, s0, s1);                   // fold_in(key(42), step)
    uint32_t r0 = 0u, r1 = (uint32_t)pidx;
    tf2x32(s0, s1, r0, r1);
    bool fire = ((r0 ^ r1) & 0x80000000u) == 0u;

    float* outb = out + bz * (CC * HH * WW);

    if (!fire) {
        pos_of[tid] = -1;
        #pragma unroll
        for (int c = 0; c < CC; c++)
            outb[(c << 16) + (gy << 8) + gx] = xs[(c * XS_ROWS + ty + 1) * 34 + tx + 1];
    } else {
        int pos = atomicAdd(cntp, 1);
        lst[pos] = tid;
        pos_of[tid] = pos;
    }
    __syncthreads();

    const int F = *cntp;
    const int NU = 2 * F;

    // ---- matvec: unit = (pixel, k-half); half-major so warps share k-range ----
    for (int u = tid; u < NU; u += NTHREADS) {
        int half = (u >= F) ? 1 : 0;
        int i    = u - half * F;
        int pt   = lst[i];
        int px = pt & 31, py = pt >> 5;

        // perceive -> packed channel pairs pp[30]
        // pp[0..9]  = (cen[2j], cen[2j+1]);  pp[10+c] = (gx_c, gy_c)
        u64 pp[30];
        float cen[20];
        #pragma unroll
        for (int c = 0; c < CC; c++) {
            const float* b = xs + (c * XS_ROWS + py) * 34 + px;
            float a00 = b[0],  a01 = b[1],  a02 = b[2];
            float a10 = b[34], a11 = b[35], a12 = b[36];
            float a20 = b[68], a21 = b[69], a22 = b[70];
            cen[c] = a11;
            float gxv = (a02 - a00 + 2.f * (a12 - a10) + a22 - a20) * 0.125f;
            float gyv = (a20 - a00 + 2.f * (a21 - a01) + a22 - a02) * 0.125f;
            pp[10 + c] = pack2(gxv, gyv);
        }
        #pragma unroll
        for (int j = 0; j < 10; j++) pp[j] = pack2(cen[2*j], cen[2*j+1]);

        u64 dxp[10];
        #pragma unroll
        for (int j = 0; j < 10; j++) dxp[j] = 0ull;

        const int k0 = half * KHALF;
        #pragma unroll 4
        for (int k = k0; k < k0 + KHALF; k++) {
            const ull2* wr = (const ull2*)(W1s + k * 60);   // 15 x 16B
            u64 a0 = 0ull, a1 = 0ull, a2 = 0ull, a3 = 0ull;
            #pragma unroll
            for (int q = 0; q < 15; q += 4) {
                { ull2 w = wr[q];   a0 = fma2(w.x, pp[2*q+0], a0);
                                    a1 = fma2(w.y, pp[2*q+1], a1); }
                if (q + 1 < 15) { ull2 w = wr[q+1]; a2 = fma2(w.x, pp[2*q+2], a2);
                                                    a3 = fma2(w.y, pp[2*q+3], a3); }
                if (q + 2 < 15) { ull2 w = wr[q+2]; a0 = fma2(w.x, pp[2*q+4], a0);
                                                    a1 = fma2(w.y, pp[2*q+5], a1); }
                if (q + 3 < 15) { ull2 w = wr[q+3]; a2 = fma2(w.x, pp[2*q+6], a2);
                                                    a3 = fma2(w.y, pp[2*q+7], a3); }
            }
            float l0, h0, l1, h1, l2, h2, l3, h3;
            unpack2(l0, h0, a0); unpack2(l1, h1, a1);
            unpack2(l2, h2, a2); unpack2(l3, h3, a3);
            float hk = ((l0 + h0) + (l1 + h1)) + ((l2 + h2) + (l3 + h3)) + b1s[k];
            hk = fmaxf(hk, 0.f);
            u64 hk2 = pack2(hk, hk);
            const ull2* w2r = (const ull2*)(W2s + k * 20);  // 5 x 16B
            #pragma unroll
            for (int q = 0; q < 5; q++) {
                ull2 w = w2r[q];
                dxp[2*q+0] = fma2(w.x, hk2, dxp[2*q+0]);
                dxp[2*q+1] = fma2(w.y, hk2, dxp[2*q+1]);
            }
        }

        // store this half's dx (exactly-once, no atomics)
        float* dr = dxs + i * DXS_STRIDE + half * 20;   // 8B-aligned
        #pragma unroll
        for (int j = 0; j < 10; j++)
            *(u64*)(dr + 2*j) = dxp[j];
    }
    __syncthreads();

    // ---- writeout for firing pixels (owner thread) ----
    const int mypos = pos_of[tid];
    if (mypos >= 0) {
        const float* d0 = dxs + mypos * DXS_STRIDE;
        const float* d1 = d0 + 20;
        #pragma unroll
        for (int c = 0; c < CC; c++) {
            float v = xs[(c * XS_ROWS + ty + 1) * 34 + tx + 1];
            if (c >= 3) v += d0[c] + d1[c];   // image channels immutable
            outb[(c << 16) + (gy << 8) + gx] = v;
        }
    }
}

extern "C" void kernel_launch(void* const* d_in, const int* in_sizes, int n_in,
                              void* d_out, int out_size) {
    // Identify inputs by unique element counts:
    // x=10485760, W1=7680, b1=128, W2=2560, steps=1
    const float* x = nullptr; const float* W1 = nullptr;
    const float* b1 = nullptr; const float* W2 = nullptr;
    for (int i = 0; i < n_in; i++) {
        switch (in_sizes[i]) {
            case BB*CC*HH*WW: x  = (const float*)d_in[i]; break;
            case W1_ELEMS:    W1 = (const float*)d_in[i]; break;
            case KH:          b1 = (const float*)d_in[i]; break;
            case W2_ELEMS:    W2 = (const float*)d_in[i]; break;
            default: break; // steps scalar; fixed at 64
        }
    }
    float* out = (float*)d_out;

    float *bufA = nullptr, *bufB = nullptr;
    cudaGetSymbolAddress((void**)&bufA, g_bufA);
    cudaGetSymbolAddress((void**)&bufB, g_bufB);

    cudaFuncSetAttribute(nca_step, cudaFuncAttributeMaxDynamicSharedMemorySize,
                         SMEM_BYTES);

    dim3 grid(WW / TILE_W, HH / TILE_H, BB);   // (8, 16, 8) = 1024 blocks
    const int STEPS = 64;
    for (int s = 0; s < STEPS; s++) {
        const float* src = (s == 0) ? x : ((s & 1) ? bufA : bufB);
        float* dst = (s == STEPS - 1) ? out : ((s & 1) ? bufB : bufA);
        nca_step<<<grid, NTHREADS, SMEM_BYTES>>>(src, dst, W1, b1, W2, s);
    }
}

// round 6
// speedup vs baseline: 1.3493x; 1.1963x over previous
#include <cuda_runtime.h>
#include <cstdint>

// NCA: x[8,20,256,256], W1[128,60], b1[128], W2[20,128], steps=64

#define BB 8
#define CC 20
#define HH 256
#define WW 256
#define KH 128
#define TILE_W 32
#define TILE_H 8
#define NTHREADS 256

#define XS_ELEMS   (CC*10*34)     // 6800
#define W1_ELEMS   (KH*60)        // 7680
#define W2_ELEMS   (KH*20)        // 2560
#define SMEM_FLOATS (XS_ELEMS + W1_ELEMS + W2_ELEMS + KH)
#define SMEM_BYTES  (SMEM_FLOATS*4 + (NTHREADS+1)*4)   // ~69.3 KB

__device__ float g_bufA[BB*CC*HH*WW];
__device__ float g_bufB[BB*CC*HH*WW];

typedef unsigned long long u64;
struct ull2 { u64 x, y; };

__device__ __forceinline__ u64 fma2(u64 a, u64 b, u64 c) {
    u64 d;
    asm("fma.rn.f32x2 %0, %1, %2, %3;" : "=l"(d) : "l"(a), "l"(b), "l"(c));
    return d;
}
__device__ __forceinline__ u64 pack2(float lo, float hi) {
    u64 r;
    asm("mov.b64 %0, {%1, %2};" : "=l"(r) : "f"(lo), "f"(hi));
    return r;
}
__device__ __forceinline__ void unpack2(float& lo, float& hi, u64 v) {
    asm("mov.b64 {%0, %1}, %2;" : "=f"(lo), "=f"(hi) : "l"(v));
}

__device__ __forceinline__ uint32_t rotl32(uint32_t v, int r) {
    return (v << r) | (v >> (32 - r));
}

// JAX threefry2x32 (20 rounds), bit-exact.
__device__ __forceinline__ void tf2x32(uint32_t k0, uint32_t k1,
                                       uint32_t& x0, uint32_t& x1) {
    uint32_t ks2 = k0 ^ k1 ^ 0x1BD11BDAu;
    x0 += k0; x1 += k1;
#define TFR(r) { x0 += x1; x1 = rotl32(x1, r); x1 ^= x0; }
    TFR(13) TFR(15) TFR(26) TFR(6)
    x0 += k1; x1 += ks2 + 1u;
    TFR(17) TFR(29) TFR(16) TFR(24)
    x0 += ks2; x1 += k0 + 2u;
    TFR(13) TFR(15) TFR(26) TFR(6)
    x0 += k0; x1 += k1 + 3u;
    TFR(17) TFR(29) TFR(16) TFR(24)
    x0 += k1; x1 += ks2 + 4u;
    TFR(13) TFR(15) TFR(26) TFR(6)
    x0 += ks2; x1 += k0 + 5u;
#undef TFR
}

__device__ __forceinline__ int refl(int v, int n) {
    v = (v < 0) ? -v : v;
    return (v >= n) ? (2 * n - 2 - v) : v;
}

__global__ void __launch_bounds__(NTHREADS, 2)
nca_step(const float* __restrict__ in, float* __restrict__ out,
         const float* __restrict__ W1, const float* __restrict__ b1,
         const float* __restrict__ W2, int step)
{
    extern __shared__ float sm[];
    float* xs  = sm;                      // [20][10][34]
    float* W1s = xs + XS_ELEMS;           // [128][60]  (240B rows, 16B aligned)
    float* W2s = W1s + W1_ELEMS;          // [128][20]  (k-major)
    float* b1s = W2s + W2_ELEMS;          // [128]
    int*   lst = (int*)(b1s + KH);        // [256] firing pixel ids
    int*   cntp = lst + NTHREADS;

    const int tid = threadIdx.x;
    const int bz  = blockIdx.z;
    const int by0 = blockIdx.y * TILE_H;
    const int bx0 = blockIdx.x * TILE_W;

    if (tid == 0) *cntp = 0;

    // ---- stage x tile (reflect halo) + weights ----
    const float* inb = in + bz * (CC * HH * WW);
    for (int i = tid; i < XS_ELEMS; i += NTHREADS) {
        int c   = i / 340;
        int rem = i - c * 340;
        int yy  = rem / 34;
        int xx  = rem - yy * 34;
        int gy  = refl(by0 + yy - 1, HH);
        int gx  = refl(bx0 + xx - 1, WW);
        xs[i] = inb[(c << 16) + (gy << 8) + gx];
    }
    for (int i = tid; i < W1_ELEMS; i += NTHREADS) W1s[i] = W1[i];
    for (int i = tid; i < W2_ELEMS; i += NTHREADS) {
        int k = i / 20; int c = i - k * 20;
        W2s[i] = W2[c * KH + k];
    }
    if (tid < KH) b1s[tid] = b1[tid];

    __syncthreads();

    const int tx = tid & 31, ty = tid >> 5;
    const int gy = by0 + ty, gx = bx0 + tx;
    const int pidx = (bz << 16) + (gy << 8) + gx;

    // ---- fire mask (partitionable threefry, XOR-fold) ----
    uint32_t s0 = 0u, s1 = (uint32_t)step;
    tf2x32(0u, 42u, s0, s1);                   // fold_in(key(42), step)
    uint32_t r0 = 0u, r1 = (uint32_t)pidx;     // block = (0, flat_idx)
    tf2x32(s0, s1, r0, r1);
    bool fire = ((r0 ^ r1) & 0x80000000u) == 0u;

    float* outb = out + bz * (CC * HH * WW);

    if (!fire) {
        #pragma unroll
        for (int c = 0; c < CC; c++)
            outb[(c << 16) + (gy << 8) + gx] = xs[(c * 10 + ty + 1) * 34 + tx + 1];
    } else {
        int pos = atomicAdd(cntp, 1);
        lst[pos] = tid;
    }
    __syncthreads();

    const int F = *cntp;
    if (tid < F) {
        const int pid = lst[tid];
        const int px = pid & 31, py = pid >> 5;

        // perceive -> packed pairs pp[30]
        // pp[0..9]  = (cen[2j], cen[2j+1]);  pp[10+c] = (gx_c, gy_c)
        u64 pp[30];
        float cen[20];
        #pragma unroll
        for (int c = 0; c < CC; c++) {
            const float* b = xs + (c * 10 + py) * 34 + px;
            float a00 = b[0],  a01 = b[1],  a02 = b[2];
            float a10 = b[34], a11 = b[35], a12 = b[36];
            float a20 = b[68], a21 = b[69], a22 = b[70];
            cen[c] = a11;
            float gxv = (a02 - a00 + 2.f * (a12 - a10) + a22 - a20) * 0.125f;
            float gyv = (a20 - a00 + 2.f * (a21 - a01) + a22 - a02) * 0.125f;
            pp[10 + c] = pack2(gxv, gyv);
        }
        #pragma unroll
        for (int j = 0; j < 10; j++) pp[j] = pack2(cen[2*j], cen[2*j+1]);

        u64 dxp[10];
        #pragma unroll
        for (int j = 0; j < 10; j++) dxp[j] = 0ull;

        #pragma unroll 4
        for (int k = 0; k < KH; k++) {
            const ull2* wr = (const ull2*)(W1s + k * 60);   // 15 x 16B
            u64 a0 = 0ull, a1 = 0ull, a2 = 0ull, a3 = 0ull;
            #pragma unroll
            for (int q = 0; q < 15; q += 2) {
                ull2 w = wr[q];
                a0 = fma2(w.x, pp[2*q+0], a0);
                a1 = fma2(w.y, pp[2*q+1], a1);
                if (q + 1 < 15) {
                    ull2 w2 = wr[q+1];
                    a2 = fma2(w2.x, pp[2*q+2], a2);
                    a3 = fma2(w2.y, pp[2*q+3], a3);
                }
            }
            float l0, h0, l1, h1, l2, h2, l3, h3;
            unpack2(l0, h0, a0); unpack2(l1, h1, a1);
            unpack2(l2, h2, a2); unpack2(l3, h3, a3);
            float hk = ((l0 + h0) + (l1 + h1)) + ((l2 + h2) + (l3 + h3)) + b1s[k];
            hk = fmaxf(hk, 0.f);
            u64 hk2 = pack2(hk, hk);
            const ull2* w2r = (const ull2*)(W2s + k * 20);  // 5 x 16B
            #pragma unroll
            for (int q = 0; q < 5; q++) {
                ull2 w = w2r[q];
                dxp[2*q+0] = fma2(w.x, hk2, dxp[2*q+0]);
                dxp[2*q+1] = fma2(w.y, hk2, dxp[2*q+1]);
            }
        }

        float dx[20];
        #pragma unroll
        for (int j = 0; j < 10; j++) unpack2(dx[2*j], dx[2*j+1], dxp[j]);

        const int ggy = by0 + py, ggx = bx0 + px;
        #pragma unroll
        for (int c = 0; c < CC; c++) {
            float v = cen[c];
            if (c >= 3) v += dx[c];           // image channels immutable
            outb[(c << 16) + (ggy << 8) + ggx] = v;
        }
    }
}

extern "C" void kernel_launch(void* const* d_in, const int* in_sizes, int n_in,
                              void* d_out, int out_size) {
    // Identify inputs by unique element counts:
    // x=10485760, W1=7680, b1=128, W2=2560, steps=1
    const float* x = nullptr; const float* W1 = nullptr;
    const float* b1 = nullptr; const float* W2 = nullptr;
    for (int i = 0; i < n_in; i++) {
        switch (in_sizes[i]) {
            case BB*CC*HH*WW: x  = (const float*)d_in[i]; break;
            case W1_ELEMS:    W1 = (const float*)d_in[i]; break;
            case KH:          b1 = (const float*)d_in[i]; break;
            case W2_ELEMS:    W2 = (const float*)d_in[i]; break;
            default: break; // steps scalar; fixed at 64
        }
    }
    float* out = (float*)d_out;

    float *bufA = nullptr, *bufB = nullptr;
    cudaGetSymbolAddress((void**)&bufA, g_bufA);
    cudaGetSymbolAddress((void**)&bufB, g_bufB);

    cudaFuncSetAttribute(nca_step, cudaFuncAttributeMaxDynamicSharedMemorySize,
                         SMEM_BYTES);

    dim3 grid(WW / TILE_W, HH / TILE_H, BB);   // (8, 32, 8) = 2048 blocks
    const int STEPS = 64;
    for (int s = 0; s < STEPS; s++) {
        const float* src = (s == 0) ? x : ((s & 1) ? bufA : bufB);
        float* dst = (s == STEPS - 1) ? out : ((s & 1) ? bufB : bufA);
        nca_step<<<grid, NTHREADS, SMEM_BYTES>>>(src, dst, W1, b1, W2, s);
    }
}